// round 5
// baseline (speedup 1.0000x reference)
#include <cuda_runtime.h>
#include <cstdint>

// Problem constants  (V, E, H, B, T = 32000, 128, 256, 16, 256)
#define VSZ 32000
#define ESZ 128           // !!! embedding dim is 128 (was wrongly 256 in R1-R3)
#define HSZ 256
#define BSZ 16
#define TSZ 256
#define G4H 1024          // 4*H
#define MTOT 4096         // T*B

// ---------------- device scratch (no cudaMalloc allowed) ----------------
__device__ float    g_xproj0[MTOT * G4H];   // [T,B,4H]
__device__ float    g_xproj1[MTOT * G4H];
__device__ float    g_h1s[MTOT * HSZ];      // [T,B,H]
__device__ float    g_h2s[MTOT * HSZ];
__device__ float    g_hbuf[4 * BSZ * HSZ];  // 2 layers x ping/pong
__device__ unsigned g_bar[2];

// ---------------- helpers ----------------
#define FMA_F32X2(acc, a, b) \
    asm("fma.rn.f32x2 %0, %1, %2, %0;" : "+l"(acc) : "l"(a), "l"(b))

__device__ __forceinline__ unsigned long long pack_dup(float v) {
    unsigned long long r;
    asm("mov.b64 %0, {%1, %1};" : "=l"(r) : "f"(v));
    return r;
}
__device__ __forceinline__ unsigned long long pack2(float x, float y) {
    unsigned long long r;
    asm("mov.b64 %0, {%1, %2};" : "=l"(r) : "f"(x), "f"(y));
    return r;
}
__device__ __forceinline__ float lo32(unsigned long long v) {
    return __uint_as_float((unsigned)(v & 0xffffffffULL));
}
__device__ __forceinline__ float hi32(unsigned long long v) {
    return __uint_as_float((unsigned)(v >> 32));
}

// ---------------- init: reset barriers + h ping-pong buffers ----------------
__global__ void init_kernel() {
    int tid = blockIdx.x * blockDim.x + threadIdx.x;
    if (tid < 2) g_bar[tid] = 0u;
    for (int i = tid; i < 4 * BSZ * HSZ; i += gridDim.x * blockDim.x)
        g_hbuf[i] = 0.f;
}

// ---------------- SGEMM: C[M,N] = A[M,K] @ W[N,K]^T + bias ----------------
// MODE 0: A gathered from emb via token ids (x_proj0)
// MODE 1: plain row-major A
// MODE 2: plain A, output remapped [t*B+b, n] -> [(b*T+t)*N + n] (logits)
template <int MODE>
__global__ __launch_bounds__(256) void sgemm_kernel(
    const float* __restrict__ A, const int* __restrict__ gidx,
    const float* __restrict__ Wt, const float* __restrict__ bias1,
    const float* __restrict__ bias2, float* __restrict__ C,
    int M, int N, int K)
{
    __shared__ float As[16][128];
    __shared__ float Bs[16][128];

    const int tid = threadIdx.x;
    const int n0 = blockIdx.x * 128;
    const int m0 = blockIdx.y * 128;

    // global load mapping: 64 rows x 16 k per pass, 2 passes
    const int lr = tid >> 2;              // 0..63
    const int lc = (tid & 3) << 2;        // 0,4,8,12

    const float* ap0;
    const float* ap1;
    {
        int mA0 = m0 + lr, mA1 = m0 + lr + 64;
        if (MODE == 0) {
            int t0 = mA0 >> 4, b0 = mA0 & 15;
            int t1 = mA1 >> 4, b1 = mA1 & 15;
            ap0 = A + (long)gidx[b0 * TSZ + t0] * K;
            ap1 = A + (long)gidx[b1 * TSZ + t1] * K;
        } else {
            ap0 = A + (long)mA0 * K;
            ap1 = A + (long)mA1 * K;
        }
    }
    const float* bp0 = Wt + (long)(n0 + lr) * K;
    const float* bp1 = Wt + (long)(n0 + lr + 64) * K;

    const int ty = tid >> 4, tx = tid & 15;
    const int row = ty << 3, col = tx << 3;

    unsigned long long acc[8][4];
#pragma unroll
    for (int i = 0; i < 8; i++)
#pragma unroll
        for (int j = 0; j < 4; j++) acc[i][j] = 0ULL;

    for (int kt = 0; kt < K; kt += 16) {
        float4 a0 = *(const float4*)(ap0 + kt + lc);
        float4 a1 = *(const float4*)(ap1 + kt + lc);
        float4 w0 = *(const float4*)(bp0 + kt + lc);
        float4 w1 = *(const float4*)(bp1 + kt + lc);
        __syncthreads();
        As[lc + 0][lr] = a0.x; As[lc + 1][lr] = a0.y;
        As[lc + 2][lr] = a0.z; As[lc + 3][lr] = a0.w;
        As[lc + 0][lr + 64] = a1.x; As[lc + 1][lr + 64] = a1.y;
        As[lc + 2][lr + 64] = a1.z; As[lc + 3][lr + 64] = a1.w;
        Bs[lc + 0][lr] = w0.x; Bs[lc + 1][lr] = w0.y;
        Bs[lc + 2][lr] = w0.z; Bs[lc + 3][lr] = w0.w;
        Bs[lc + 0][lr + 64] = w1.x; Bs[lc + 1][lr + 64] = w1.y;
        Bs[lc + 2][lr + 64] = w1.z; Bs[lc + 3][lr + 64] = w1.w;
        __syncthreads();

#pragma unroll
        for (int k = 0; k < 16; k++) {
            float4 av0 = *(const float4*)&As[k][row];
            float4 av1 = *(const float4*)&As[k][row + 4];
            float4 bq0 = *(const float4*)&Bs[k][col];
            float4 bq1 = *(const float4*)&Bs[k][col + 4];
            unsigned long long bv0 = pack2(bq0.x, bq0.y);
            unsigned long long bv1 = pack2(bq0.z, bq0.w);
            unsigned long long bv2 = pack2(bq1.x, bq1.y);
            unsigned long long bv3 = pack2(bq1.z, bq1.w);
            float av[8] = {av0.x, av0.y, av0.z, av0.w, av1.x, av1.y, av1.z, av1.w};
#pragma unroll
            for (int i = 0; i < 8; i++) {
                unsigned long long a2 = pack_dup(av[i]);
                FMA_F32X2(acc[i][0], a2, bv0);
                FMA_F32X2(acc[i][1], a2, bv1);
                FMA_F32X2(acc[i][2], a2, bv2);
                FMA_F32X2(acc[i][3], a2, bv3);
            }
        }
    }

#pragma unroll
    for (int i = 0; i < 8; i++) {
        int m = m0 + row + i;
        long base;
        if (MODE == 2) {
            int t = m >> 4, b = m & 15;
            base = ((long)b * TSZ + t) * (long)N;
        } else {
            base = (long)m * N;
        }
#pragma unroll
        for (int j = 0; j < 4; j++) {
            int n = n0 + col + 2 * j;
            float b0 = bias1[n] + (bias2 ? bias2[n] : 0.f);
            float b1 = bias1[n + 1] + (bias2 ? bias2[n + 1] : 0.f);
            C[base + n] = lo32(acc[i][j]) + b0;
            C[base + n + 1] = hi32(acc[i][j]) + b1;
        }
    }
}

// ---------------- persistent LSTM layer ----------------
// Grid: 64 CTAs x 256 threads. CTA owns 4 h-columns (16 gate rows of W_hh,
// kept in SMEM across all timesteps). Per step: read full h from ping-pong
// global buffer (L2 via __ldcg), compute gates, exchange via SMEM, 64 update
// threads hold c in registers, write h slice with __stcg, grid spin-barrier.
__global__ __launch_bounds__(256, 1) void lstm_layer_kernel(
    const float* __restrict__ xproj,  // [T,B,4H] already includes b_ih + b_hh
    const float* __restrict__ W_hh,   // [4H,H]
    float* __restrict__ hb0, float* __restrict__ hb1,  // ping-pong [B,H]
    float* __restrict__ hs,           // [T,B,H] output sequence
    float* __restrict__ h_fin, float* __restrict__ c_fin,  // [B,H] or null
    unsigned* __restrict__ bar)
{
    __shared__ float2 Ws2[128][16];       // [k/2][r] pairs of W along k
    __shared__ float  hs_s[BSZ * HSZ];    // full h, 16KB
    __shared__ float  gbuf[16][17];

    const int tid = threadIdx.x;
    const int j0 = blockIdx.x * 4;

    // preload this CTA's 16 W_hh rows (r = g*4 + jj -> row g*H + j0 + jj)
    for (int idx = tid; idx < 16 * HSZ; idx += 256) {
        int k = idx >> 4;
        int r = idx & 15;
        int g = r >> 2, jj = r & 3;
        float v = W_hh[(g * HSZ + j0 + jj) * HSZ + k];
        ((float*)Ws2)[(k >> 1) * 32 + r * 2 + (k & 1)] = v;
    }
    __syncthreads();

    const int b = tid >> 4, r = tid & 15;
    const int gcol = (r >> 2) * HSZ + j0 + (r & 3);
    const int ub = tid >> 2, ujj = tid & 3;   // update threads (tid < 64)

    float c_st = 0.f, h_st = 0.f;
    unsigned target = 0;
    float* hb[2] = {hb0, hb1};

    for (int t = 0; t < TSZ; t++) {
        // stage h(t-1) into smem (L2-coherent path)
        {
            const float4* src = (const float4*)hb[t & 1];
            float4* dst = (float4*)hs_s;
#pragma unroll
            for (int j = 0; j < 4; j++) dst[tid + 256 * j] = __ldcg(src + tid + 256 * j);
        }
        __syncthreads();

        // dot(h[b,:], W_hh[row(r),:]) with packed f32x2
        unsigned long long accA = 0ULL, accB = 0ULL;
        const unsigned long long* hrow = (const unsigned long long*)(hs_s + b * HSZ);
#pragma unroll 16
        for (int k2 = 0; k2 < 128; k2 += 2) {
            unsigned long long h0 = hrow[k2];
            unsigned long long h1 = hrow[k2 + 1];
            unsigned long long w0 = *(const unsigned long long*)&Ws2[k2][r];
            unsigned long long w1 = *(const unsigned long long*)&Ws2[k2 + 1][r];
            FMA_F32X2(accA, h0, w0);
            FMA_F32X2(accB, h1, w1);
        }
        float acc = (lo32(accA) + hi32(accA)) + (lo32(accB) + hi32(accB));
        acc += xproj[(t * BSZ + b) * G4H + gcol];
        gbuf[b][r] = acc;
        __syncthreads();

        if (tid < 64) {
            float iv = gbuf[ub][ujj];
            float fv = gbuf[ub][4 + ujj];
            float gv = gbuf[ub][8 + ujj];
            float ov = gbuf[ub][12 + ujj];
            iv = 1.f / (1.f + expf(-iv));
            fv = 1.f / (1.f + expf(-fv));
            ov = 1.f / (1.f + expf(-ov));
            gv = tanhf(gv);
            c_st = fv * c_st + iv * gv;
            h_st = ov * tanhf(c_st);
            int hcol = j0 + ujj;
            __stcg(&hb[(t + 1) & 1][ub * HSZ + hcol], h_st);  // straight to L2
            hs[(t * BSZ + ub) * HSZ + hcol] = h_st;
        }
        __syncthreads();

        // device-wide barrier (monotonic counter; release/acquire)
        target += 64;
        if (tid == 0) {
            asm volatile("red.release.gpu.global.add.u32 [%0], 1;" :: "l"(bar) : "memory");
            unsigned v;
            do {
                asm volatile("ld.acquire.gpu.global.u32 %0, [%1];" : "=r"(v) : "l"(bar));
            } while (v < target);
        }
        __syncthreads();
    }

    if (tid < 64 && h_fin != nullptr) {
        h_fin[ub * HSZ + j0 + ujj] = h_st;
        c_fin[ub * HSZ + j0 + ujj] = c_st;
    }
}

// ---------------- launch ----------------
extern "C" void kernel_launch(void* const* d_in, const int* in_sizes, int n_in,
                              void* d_out, int out_size) {
    const int*   x     = (const int*)d_in[0];
    const float* emb   = (const float*)d_in[1];
    const float* W_ih0 = (const float*)d_in[2];
    const float* W_hh0 = (const float*)d_in[3];
    const float* b_ih0 = (const float*)d_in[4];
    const float* b_hh0 = (const float*)d_in[5];
    const float* W_ih1 = (const float*)d_in[6];
    const float* W_hh1 = (const float*)d_in[7];
    const float* b_ih1 = (const float*)d_in[8];
    const float* b_hh1 = (const float*)d_in[9];
    const float* W_fc  = (const float*)d_in[10];
    const float* b_fc  = (const float*)d_in[11];
    float* out = (float*)d_out;

    float *xp0, *xp1, *h1s, *h2s, *hb;
    unsigned* bars;
    cudaGetSymbolAddress((void**)&xp0,  g_xproj0);
    cudaGetSymbolAddress((void**)&xp1,  g_xproj1);
    cudaGetSymbolAddress((void**)&h1s,  g_h1s);
    cudaGetSymbolAddress((void**)&h2s,  g_h2s);
    cudaGetSymbolAddress((void**)&hb,   g_hbuf);
    cudaGetSymbolAddress((void**)&bars, g_bar);

    const long OFF_H = (long)BSZ * TSZ * VSZ;           // logits size
    const long OFF_C = OFF_H + 2L * BSZ * HSZ;
    const bool ws = ((long)out_size >= OFF_C + 2L * BSZ * HSZ);
    float* hf0 = ws ? out + OFF_H : nullptr;
    float* hf1 = ws ? out + OFF_H + BSZ * HSZ : nullptr;
    float* cf0 = ws ? out + OFF_C : nullptr;
    float* cf1 = ws ? out + OFF_C + BSZ * HSZ : nullptr;

    init_kernel<<<8, 256>>>();

    dim3 gproj(G4H / 128, MTOT / 128);   // (8, 32)
    sgemm_kernel<0><<<gproj, 256>>>(emb, x, W_ih0, b_ih0, b_hh0, xp0,
                                    MTOT, G4H, ESZ);   // K = E = 128
    lstm_layer_kernel<<<64, 256>>>(xp0, W_hh0, hb, hb + BSZ * HSZ,
                                   h1s, hf0, cf0, bars + 0);
    sgemm_kernel<1><<<gproj, 256>>>(h1s, nullptr, W_ih1, b_ih1, b_hh1, xp1,
                                    MTOT, G4H, HSZ);
    lstm_layer_kernel<<<64, 256>>>(xp1, W_hh1, hb + 2 * BSZ * HSZ, hb + 3 * BSZ * HSZ,
                                   h2s, hf1, cf1, bars + 1);
    dim3 glog(VSZ / 128, MTOT / 128);    // (250, 32)
    sgemm_kernel<2><<<glog, 256>>>(h2s, nullptr, W_fc, b_fc, nullptr, out,
                                   MTOT, VSZ, HSZ);
}

// round 7
// speedup vs baseline: 1.4815x; 1.4815x over previous
#include <cuda_runtime.h>
#include <cuda_bf16.h>
#include <cstdint>

// Problem constants  (V, E, H, B, T = 32000, 128, 256, 16, 256)
#define VSZ 32000
#define ESZ 128
#define HSZ 256
#define BSZ 16
#define TSZ 256
#define G4H 1024          // 4*H
#define MTOT 4096         // T*B

// ---------------- device scratch (no cudaMalloc allowed) ----------------
__device__ float    g_xproj0[MTOT * G4H];   // [T,B,4H]
__device__ float    g_xproj1[MTOT * G4H];
__device__ float    g_h1s[MTOT * HSZ];      // [T,B,H]
__device__ float    g_h2s[MTOT * HSZ];
__device__ float    g_hbuf[4 * BSZ * HSZ];  // 2 layers x ping/pong
__device__ unsigned g_bar[2];
// split-bf16 operands for the HMMA logits GEMM
__device__ __nv_bfloat16 g_whi[VSZ * HSZ];
__device__ __nv_bfloat16 g_wlo[VSZ * HSZ];
__device__ __nv_bfloat16 g_ahi[MTOT * HSZ];
__device__ __nv_bfloat16 g_alo[MTOT * HSZ];

// ---------------- helpers ----------------
#define FMA_F32X2(acc, a, b) \
    asm("fma.rn.f32x2 %0, %1, %2, %0;" : "+l"(acc) : "l"(a), "l"(b))

__device__ __forceinline__ unsigned long long pack_dup(float v) {
    unsigned long long r;
    asm("mov.b64 %0, {%1, %1};" : "=l"(r) : "f"(v));
    return r;
}
__device__ __forceinline__ unsigned long long pack2(float x, float y) {
    unsigned long long r;
    asm("mov.b64 %0, {%1, %2};" : "=l"(r) : "f"(x), "f"(y));
    return r;
}
__device__ __forceinline__ float lo32(unsigned long long v) {
    return __uint_as_float((unsigned)(v & 0xffffffffULL));
}
__device__ __forceinline__ float hi32(unsigned long long v) {
    return __uint_as_float((unsigned)(v >> 32));
}
__device__ __forceinline__ uint32_t smem_u32(const void* p) {
    uint32_t a;
    asm("{ .reg .u64 t; cvta.to.shared.u64 t, %1; cvt.u32.u64 %0, t; }"
        : "=r"(a) : "l"(p));
    return a;
}
__device__ __forceinline__ void cp16(uint32_t s, const void* g) {
    asm volatile("cp.async.cg.shared.global [%0], [%1], 16;"
                 :: "r"(s), "l"(g) : "memory");
}
__device__ __forceinline__ void ldm_x4(uint32_t* r, uint32_t addr) {
    asm volatile("ldmatrix.sync.aligned.m8n8.x4.shared.b16 {%0,%1,%2,%3}, [%4];"
                 : "=r"(r[0]), "=r"(r[1]), "=r"(r[2]), "=r"(r[3]) : "r"(addr));
}
__device__ __forceinline__ void mma_bf16(float* d, const uint32_t* a, const uint32_t* b) {
    asm volatile(
        "mma.sync.aligned.m16n8k16.row.col.f32.bf16.bf16.f32 "
        "{%0,%1,%2,%3}, {%4,%5,%6,%7}, {%8,%9}, {%0,%1,%2,%3};"
        : "+f"(d[0]), "+f"(d[1]), "+f"(d[2]), "+f"(d[3])
        : "r"(a[0]), "r"(a[1]), "r"(a[2]), "r"(a[3]), "r"(b[0]), "r"(b[1]));
}

// ---------------- init ----------------
__global__ void init_kernel() {
    int tid = blockIdx.x * blockDim.x + threadIdx.x;
    if (tid < 2) g_bar[tid] = 0u;
    for (int i = tid; i < 4 * BSZ * HSZ; i += gridDim.x * blockDim.x)
        g_hbuf[i] = 0.f;
}

// ---------------- split f32 -> bf16 hi + lo ----------------
__global__ void cvt_split_kernel(const float* __restrict__ src,
                                 __nv_bfloat16* __restrict__ hi,
                                 __nv_bfloat16* __restrict__ lo, int n4) {
    int stride = gridDim.x * blockDim.x;
    const float4* s4 = (const float4*)src;
    unsigned long long* h8 = (unsigned long long*)hi;
    unsigned long long* l8 = (unsigned long long*)lo;
    for (int i = blockIdx.x * blockDim.x + threadIdx.x; i < n4; i += stride) {
        float4 v = s4[i];
        __nv_bfloat16 h0 = __float2bfloat16_rn(v.x);
        __nv_bfloat16 h1 = __float2bfloat16_rn(v.y);
        __nv_bfloat16 h2 = __float2bfloat16_rn(v.z);
        __nv_bfloat16 h3 = __float2bfloat16_rn(v.w);
        __nv_bfloat16 l0 = __float2bfloat16_rn(v.x - __bfloat162float(h0));
        __nv_bfloat16 l1 = __float2bfloat16_rn(v.y - __bfloat162float(h1));
        __nv_bfloat16 l2 = __float2bfloat16_rn(v.z - __bfloat162float(h2));
        __nv_bfloat16 l3 = __float2bfloat16_rn(v.w - __bfloat162float(h3));
        unsigned long long ph =
            (unsigned long long)__bfloat16_as_ushort(h0) |
            ((unsigned long long)__bfloat16_as_ushort(h1) << 16) |
            ((unsigned long long)__bfloat16_as_ushort(h2) << 32) |
            ((unsigned long long)__bfloat16_as_ushort(h3) << 48);
        unsigned long long pl =
            (unsigned long long)__bfloat16_as_ushort(l0) |
            ((unsigned long long)__bfloat16_as_ushort(l1) << 16) |
            ((unsigned long long)__bfloat16_as_ushort(l2) << 32) |
            ((unsigned long long)__bfloat16_as_ushort(l3) << 48);
        h8[i] = ph;
        l8[i] = pl;
    }
}

// ---------------- HMMA logits GEMM ----------------
// D[4096,32000] = A[4096,256] @ W[32000,256]^T + b,  split-bf16 (3 terms).
// CTA tile 128x128, 8 warps as 4(m) x 2(n), warp tile 32x64.
// K chunks of 64, cp.async double-buffered.
// SMEM stage (65536B): Ahi[128][64] @0, Alo @16384, Whi @32768, Wlo @49152,
// bf16, row=128B with 16B-chunk xor-swizzle (chunk ^ (row&7)).
// Output remap [t*16+b, n] -> [(b*256+t)*32000 + n].
#define LOGITS_SMEM 131072
__global__ __launch_bounds__(256, 1) void logits_hmma_kernel(
    const __nv_bfloat16* __restrict__ Ahi, const __nv_bfloat16* __restrict__ Alo,
    const __nv_bfloat16* __restrict__ Whi, const __nv_bfloat16* __restrict__ Wlo,
    const float* __restrict__ bias, float* __restrict__ out)
{
    extern __shared__ char smem[];
    __shared__ float sbias[128];
    const int tid = threadIdx.x, lane = tid & 31, w = tid >> 5;
    const int wm = w >> 1, wn = w & 1;
    const int n0 = blockIdx.x * 128;
    const int m0 = blockIdx.y * 128;
    const uint32_t sb = smem_u32(smem);

    if (tid < 128) sbias[tid] = bias[n0 + tid];

    // ---- async loader for K-chunk c into stage s ----
    auto issue = [&](int c, int s) {
        uint32_t st = sb + s * 65536;
#pragma unroll
        for (int i = 0; i < 4; i++) {
            int lin = tid + i * 256;
            int row = lin >> 3, ch = lin & 7;
            uint32_t phys = row * 128 + ((ch ^ (row & 7)) << 4);
            size_t ga = (size_t)(m0 + row) * HSZ + c * 64 + ch * 8;
            size_t gb = (size_t)(n0 + row) * HSZ + c * 64 + ch * 8;
            cp16(st + phys,         Ahi + ga);
            cp16(st + 16384 + phys, Alo + ga);
            cp16(st + 32768 + phys, Whi + gb);
            cp16(st + 49152 + phys, Wlo + gb);
        }
        asm volatile("cp.async.commit_group;" ::: "memory");
    };

    float d[2][8][4];
#pragma unroll
    for (int mt = 0; mt < 2; mt++)
#pragma unroll
        for (int nt = 0; nt < 8; nt++)
#pragma unroll
            for (int j = 0; j < 4; j++) d[mt][nt][j] = 0.f;

    issue(0, 0);

    for (int c = 0; c < 4; c++) {
        const int s = c & 1;
        if (c < 3) {
            issue(c + 1, s ^ 1);
            asm volatile("cp.async.wait_group 1;" ::: "memory");
        } else {
            asm volatile("cp.async.wait_group 0;" ::: "memory");
        }
        __syncthreads();

        const uint32_t st = sb + s * 65536;
#pragma unroll
        for (int ks = 0; ks < 4; ks++) {
            uint32_t ahf[2][4], alf[2][4];
#pragma unroll
            for (int mt = 0; mt < 2; mt++) {
                int row = wm * 32 + mt * 16 + (lane & 7) + ((lane >> 3) & 1) * 8;
                int ch = ks * 2 + ((lane >> 4) & 1);
                uint32_t ad = st + row * 128 + ((ch ^ (row & 7)) << 4);
                ldm_x4(ahf[mt], ad);
                ldm_x4(alf[mt], ad + 16384);
            }
            uint32_t bhf[8][2], blf[8][2];
#pragma unroll
            for (int nt2 = 0; nt2 < 4; nt2++) {
                int row = wn * 64 + nt2 * 16 + (lane & 7) + ((lane >> 4) & 1) * 8;
                int ch = ks * 2 + ((lane >> 3) & 1);
                uint32_t ad = st + 32768 + row * 128 + ((ch ^ (row & 7)) << 4);
                uint32_t q[4];
                ldm_x4(q, ad);
                bhf[2 * nt2][0] = q[0]; bhf[2 * nt2][1] = q[1];
                bhf[2 * nt2 + 1][0] = q[2]; bhf[2 * nt2 + 1][1] = q[3];
                ldm_x4(q, ad + 16384);
                blf[2 * nt2][0] = q[0]; blf[2 * nt2][1] = q[1];
                blf[2 * nt2 + 1][0] = q[2]; blf[2 * nt2 + 1][1] = q[3];
            }
#pragma unroll
            for (int mt = 0; mt < 2; mt++)
#pragma unroll
                for (int nt = 0; nt < 8; nt++) {
                    mma_bf16(d[mt][nt], ahf[mt], bhf[nt]);  // hi*hi
                    mma_bf16(d[mt][nt], ahf[mt], blf[nt]);  // hi*lo
                    mma_bf16(d[mt][nt], alf[mt], bhf[nt]);  // lo*hi
                }
        }
        __syncthreads();
    }

    // ---- epilogue: bias + [t,b]->[b,t] remapped store ----
#pragma unroll
    for (int mt = 0; mt < 2; mt++) {
        int mrow = m0 + wm * 32 + mt * 16 + (lane >> 2);
#pragma unroll
        for (int half = 0; half < 2; half++) {
            int m = mrow + half * 8;
            int t = m >> 4, b = m & 15;
            float* dst = out + ((long)b * TSZ + t) * (long)VSZ + n0;
#pragma unroll
            for (int nt = 0; nt < 8; nt++) {
                int lc = wn * 64 + nt * 8 + (lane & 3) * 2;
                float2 v;
                v.x = d[mt][nt][half * 2 + 0] + sbias[lc];
                v.y = d[mt][nt][half * 2 + 1] + sbias[lc + 1];
                *(float2*)(dst + lc) = v;
            }
        }
    }
}

// ---------------- SGEMM: C[M,N] = A[M,K] @ W[N,K]^T + bias ----------------
// MODE 0: A gathered from emb via token ids (x_proj0);  MODE 1: plain A
template <int MODE>
__global__ __launch_bounds__(256) void sgemm_kernel(
    const float* __restrict__ A, const int* __restrict__ gidx,
    const float* __restrict__ Wt, const float* __restrict__ bias1,
    const float* __restrict__ bias2, float* __restrict__ C,
    int M, int N, int K)
{
    __shared__ float As[16][128];
    __shared__ float Bs[16][128];

    const int tid = threadIdx.x;
    const int n0 = blockIdx.x * 128;
    const int m0 = blockIdx.y * 128;

    const int lr = tid >> 2;              // 0..63
    const int lc = (tid & 3) << 2;        // 0,4,8,12

    const float* ap0;
    const float* ap1;
    {
        int mA0 = m0 + lr, mA1 = m0 + lr + 64;
        if (MODE == 0) {
            int t0 = mA0 >> 4, b0 = mA0 & 15;
            int t1 = mA1 >> 4, b1 = mA1 & 15;
            ap0 = A + (long)gidx[b0 * TSZ + t0] * K;
            ap1 = A + (long)gidx[b1 * TSZ + t1] * K;
        } else {
            ap0 = A + (long)mA0 * K;
            ap1 = A + (long)mA1 * K;
        }
    }
    const float* bp0 = Wt + (long)(n0 + lr) * K;
    const float* bp1 = Wt + (long)(n0 + lr + 64) * K;

    const int ty = tid >> 4, tx = tid & 15;
    const int row = ty << 3, col = tx << 3;

    unsigned long long acc[8][4];
#pragma unroll
    for (int i = 0; i < 8; i++)
#pragma unroll
        for (int j = 0; j < 4; j++) acc[i][j] = 0ULL;

    for (int kt = 0; kt < K; kt += 16) {
        float4 a0 = *(const float4*)(ap0 + kt + lc);
        float4 a1 = *(const float4*)(ap1 + kt + lc);
        float4 w0 = *(const float4*)(bp0 + kt + lc);
        float4 w1 = *(const float4*)(bp1 + kt + lc);
        __syncthreads();
        As[lc + 0][lr] = a0.x; As[lc + 1][lr] = a0.y;
        As[lc + 2][lr] = a0.z; As[lc + 3][lr] = a0.w;
        As[lc + 0][lr + 64] = a1.x; As[lc + 1][lr + 64] = a1.y;
        As[lc + 2][lr + 64] = a1.z; As[lc + 3][lr + 64] = a1.w;
        Bs[lc + 0][lr] = w0.x; Bs[lc + 1][lr] = w0.y;
        Bs[lc + 2][lr] = w0.z; Bs[lc + 3][lr] = w0.w;
        Bs[lc + 0][lr + 64] = w1.x; Bs[lc + 1][lr + 64] = w1.y;
        Bs[lc + 2][lr + 64] = w1.z; Bs[lc + 3][lr + 64] = w1.w;
        __syncthreads();

#pragma unroll
        for (int k = 0; k < 16; k++) {
            float4 av0 = *(const float4*)&As[k][row];
            float4 av1 = *(const float4*)&As[k][row + 4];
            float4 bq0 = *(const float4*)&Bs[k][col];
            float4 bq1 = *(const float4*)&Bs[k][col + 4];
            unsigned long long bv0 = pack2(bq0.x, bq0.y);
            unsigned long long bv1 = pack2(bq0.z, bq0.w);
            unsigned long long bv2 = pack2(bq1.x, bq1.y);
            unsigned long long bv3 = pack2(bq1.z, bq1.w);
            float av[8] = {av0.x, av0.y, av0.z, av0.w, av1.x, av1.y, av1.z, av1.w};
#pragma unroll
            for (int i = 0; i < 8; i++) {
                unsigned long long a2 = pack_dup(av[i]);
                FMA_F32X2(acc[i][0], a2, bv0);
                FMA_F32X2(acc[i][1], a2, bv1);
                FMA_F32X2(acc[i][2], a2, bv2);
                FMA_F32X2(acc[i][3], a2, bv3);
            }
        }
    }

#pragma unroll
    for (int i = 0; i < 8; i++) {
        int m = m0 + row + i;
        long base = (long)m * N;
#pragma unroll
        for (int j = 0; j < 4; j++) {
            int n = n0 + col + 2 * j;
            float b0 = bias1[n] + (bias2 ? bias2[n] : 0.f);
            float b1 = bias1[n + 1] + (bias2 ? bias2[n + 1] : 0.f);
            C[base + n] = lo32(acc[i][j]) + b0;
            C[base + n + 1] = hi32(acc[i][j]) + b1;
        }
    }
}

// ---------------- persistent LSTM layer ----------------
__global__ __launch_bounds__(256, 1) void lstm_layer_kernel(
    const float* __restrict__ xproj,  // [T,B,4H] already includes b_ih + b_hh
    const float* __restrict__ W_hh,   // [4H,H]
    float* __restrict__ hb0, float* __restrict__ hb1,  // ping-pong [B,H]
    float* __restrict__ hs,           // [T,B,H] output sequence
    float* __restrict__ h_fin, float* __restrict__ c_fin,  // [B,H] or null
    unsigned* __restrict__ bar)
{
    __shared__ float2 Ws2[128][16];       // [k/2][r] pairs of W along k
    __shared__ float  hs_s[BSZ * HSZ];    // full h, 16KB
    __shared__ float  gbuf[16][17];

    const int tid = threadIdx.x;
    const int j0 = blockIdx.x * 4;

    for (int idx = tid; idx < 16 * HSZ; idx += 256) {
        int k = idx >> 4;
        int r = idx & 15;
        int g = r >> 2, jj = r & 3;
        float v = W_hh[(g * HSZ + j0 + jj) * HSZ + k];
        ((float*)Ws2)[(k >> 1) * 32 + r * 2 + (k & 1)] = v;
    }
    __syncthreads();

    const int b = tid >> 4, r = tid & 15;
    const int gcol = (r >> 2) * HSZ + j0 + (r & 3);
    const int ub = tid >> 2, ujj = tid & 3;   // update threads (tid < 64)

    float c_st = 0.f, h_st = 0.f;
    unsigned target = 0;
    float* hb[2] = {hb0, hb1};

    for (int t = 0; t < TSZ; t++) {
        {
            const float4* src = (const float4*)hb[t & 1];
            float4* dst = (float4*)hs_s;
#pragma unroll
            for (int j = 0; j < 4; j++) dst[tid + 256 * j] = __ldcg(src + tid + 256 * j);
        }
        __syncthreads();

        unsigned long long accA = 0ULL, accB = 0ULL;
        const unsigned long long* hrow = (const unsigned long long*)(hs_s + b * HSZ);
#pragma unroll 16
        for (int k2 = 0; k2 < 128; k2 += 2) {
            unsigned long long h0 = hrow[k2];
            unsigned long long h1 = hrow[k2 + 1];
            unsigned long long w0 = *(const unsigned long long*)&Ws2[k2][r];
            unsigned long long w1 = *(const unsigned long long*)&Ws2[k2 + 1][r];
            FMA_F32X2(accA, h0, w0);
            FMA_F32X2(accB, h1, w1);
        }
        float acc = (lo32(accA) + hi32(accA)) + (lo32(accB) + hi32(accB));
        acc += xproj[(t * BSZ + b) * G4H + gcol];
        gbuf[b][r] = acc;
        __syncthreads();

        if (tid < 64) {
            float iv = gbuf[ub][ujj];
            float fv = gbuf[ub][4 + ujj];
            float gv = gbuf[ub][8 + ujj];
            float ov = gbuf[ub][12 + ujj];
            iv = 1.f / (1.f + expf(-iv));
            fv = 1.f / (1.f + expf(-fv));
            ov = 1.f / (1.f + expf(-ov));
            gv = tanhf(gv);
            c_st = fv * c_st + iv * gv;
            h_st = ov * tanhf(c_st);
            int hcol = j0 + ujj;
            __stcg(&hb[(t + 1) & 1][ub * HSZ + hcol], h_st);
            hs[(t * BSZ + ub) * HSZ + hcol] = h_st;
        }
        __syncthreads();

        target += 64;
        if (tid == 0) {
            asm volatile("red.release.gpu.global.add.u32 [%0], 1;" :: "l"(bar) : "memory");
            unsigned v;
            do {
                asm volatile("ld.acquire.gpu.global.u32 %0, [%1];" : "=r"(v) : "l"(bar));
            } while (v < target);
        }
        __syncthreads();
    }

    if (tid < 64 && h_fin != nullptr) {
        h_fin[ub * HSZ + j0 + ujj] = h_st;
        c_fin[ub * HSZ + j0 + ujj] = c_st;
    }
}

// ---------------- launch ----------------
extern "C" void kernel_launch(void* const* d_in, const int* in_sizes, int n_in,
                              void* d_out, int out_size) {
    const int*   x     = (const int*)d_in[0];
    const float* emb   = (const float*)d_in[1];
    const float* W_ih0 = (const float*)d_in[2];
    const float* W_hh0 = (const float*)d_in[3];
    const float* b_ih0 = (const float*)d_in[4];
    const float* b_hh0 = (const float*)d_in[5];
    const float* W_ih1 = (const float*)d_in[6];
    const float* W_hh1 = (const float*)d_in[7];
    const float* b_ih1 = (const float*)d_in[8];
    const float* b_hh1 = (const float*)d_in[9];
    const float* W_fc  = (const float*)d_in[10];
    const float* b_fc  = (const float*)d_in[11];
    float* out = (float*)d_out;

    float *xp0, *xp1, *h1s, *h2s, *hb;
    unsigned* bars;
    __nv_bfloat16 *whi, *wlo, *ahi, *alo;
    cudaGetSymbolAddress((void**)&xp0,  g_xproj0);
    cudaGetSymbolAddress((void**)&xp1,  g_xproj1);
    cudaGetSymbolAddress((void**)&h1s,  g_h1s);
    cudaGetSymbolAddress((void**)&h2s,  g_h2s);
    cudaGetSymbolAddress((void**)&hb,   g_hbuf);
    cudaGetSymbolAddress((void**)&bars, g_bar);
    cudaGetSymbolAddress((void**)&whi,  g_whi);
    cudaGetSymbolAddress((void**)&wlo,  g_wlo);
    cudaGetSymbolAddress((void**)&ahi,  g_ahi);
    cudaGetSymbolAddress((void**)&alo,  g_alo);

    cudaFuncSetAttribute(logits_hmma_kernel,
                         cudaFuncAttributeMaxDynamicSharedMemorySize, LOGITS_SMEM);

    const long OFF_H = (long)BSZ * TSZ * VSZ;           // logits size
    const long OFF_C = OFF_H + 2L * BSZ * HSZ;
    const bool ws = ((long)out_size >= OFF_C + 2L * BSZ * HSZ);
    float* hf0 = ws ? out + OFF_H : nullptr;
    float* hf1 = ws ? out + OFF_H + BSZ * HSZ : nullptr;
    float* cf0 = ws ? out + OFF_C : nullptr;
    float* cf1 = ws ? out + OFF_C + BSZ * HSZ : nullptr;

    init_kernel<<<8, 256>>>();
    // W_fc split-bf16 conversion (independent of LSTM path)
    cvt_split_kernel<<<2048, 256>>>(W_fc, whi, wlo, VSZ * HSZ / 4);

    dim3 gproj(G4H / 128, MTOT / 128);   // (8, 32)
    sgemm_kernel<0><<<gproj, 256>>>(emb, x, W_ih0, b_ih0, b_hh0, xp0,
                                    MTOT, G4H, ESZ);
    lstm_layer_kernel<<<64, 256>>>(xp0, W_hh0, hb, hb + BSZ * HSZ,
                                   h1s, hf0, cf0, bars + 0);
    sgemm_kernel<1><<<gproj, 256>>>(h1s, nullptr, W_ih1, b_ih1, b_hh1, xp1,
                                    MTOT, G4H, HSZ);
    lstm_layer_kernel<<<64, 256>>>(xp1, W_hh1, hb + 2 * BSZ * HSZ, hb + 3 * BSZ * HSZ,
                                   h2s, hf1, cf1, bars + 1);
    // A split-bf16 conversion, then HMMA logits GEMM
    cvt_split_kernel<<<512, 256>>>(h2s, ahi, alo, MTOT * HSZ / 4);
    dim3 glog(VSZ / 128, MTOT / 128);    // (250, 32)
    logits_hmma_kernel<<<glog, 256, LOGITS_SMEM>>>(ahi, alo, whi, wlo, b_fc, out);
}

// round 8
// speedup vs baseline: 1.9576x; 1.3214x over previous
#include <cuda_runtime.h>
#include <cuda_bf16.h>
#include <cstdint>

// Problem constants  (V, E, H, B, T = 32000, 128, 256, 16, 256)
#define VSZ 32000
#define ESZ 128
#define HSZ 256
#define BSZ 16
#define TSZ 256
#define G4H 1024          // 4*H
#define MTOT 4096         // T*B

// ---------------- device scratch (no cudaMalloc allowed) ----------------
__device__ float    g_xproj0[MTOT * G4H];   // [T,B,4H]
__device__ float    g_h1s[MTOT * HSZ];      // [T,B,H]
__device__ float    g_h2s[MTOT * HSZ];
__device__ float    g_hbuf[4 * BSZ * HSZ];  // L0 ping/pong, L1 ping/pong
__device__ unsigned g_bar[2];
// split-bf16 operands for the HMMA logits GEMM
__device__ __nv_bfloat16 g_whi[VSZ * HSZ];
__device__ __nv_bfloat16 g_wlo[VSZ * HSZ];
__device__ __nv_bfloat16 g_ahi[MTOT * HSZ];
__device__ __nv_bfloat16 g_alo[MTOT * HSZ];

// ---------------- helpers ----------------
#define FMA_F32X2(acc, a, b) \
    asm("fma.rn.f32x2 %0, %1, %2, %0;" : "+l"(acc) : "l"(a), "l"(b))

__device__ __forceinline__ unsigned long long pack_dup(float v) {
    unsigned long long r;
    asm("mov.b64 %0, {%1, %1};" : "=l"(r) : "f"(v));
    return r;
}
__device__ __forceinline__ unsigned long long pack2(float x, float y) {
    unsigned long long r;
    asm("mov.b64 %0, {%1, %2};" : "=l"(r) : "f"(x), "f"(y));
    return r;
}
__device__ __forceinline__ float lo32(unsigned long long v) {
    return __uint_as_float((unsigned)(v & 0xffffffffULL));
}
__device__ __forceinline__ float hi32(unsigned long long v) {
    return __uint_as_float((unsigned)(v >> 32));
}
__device__ __forceinline__ uint32_t smem_u32(const void* p) {
    uint32_t a;
    asm("{ .reg .u64 t; cvta.to.shared.u64 t, %1; cvt.u32.u64 %0, t; }"
        : "=r"(a) : "l"(p));
    return a;
}
__device__ __forceinline__ void cp16(uint32_t s, const void* g) {
    asm volatile("cp.async.cg.shared.global [%0], [%1], 16;"
                 :: "r"(s), "l"(g) : "memory");
}
__device__ __forceinline__ void ldm_x4(uint32_t* r, uint32_t addr) {
    asm volatile("ldmatrix.sync.aligned.m8n8.x4.shared.b16 {%0,%1,%2,%3}, [%4];"
                 : "=r"(r[0]), "=r"(r[1]), "=r"(r[2]), "=r"(r[3]) : "r"(addr));
}
__device__ __forceinline__ void mma_bf16(float* d, const uint32_t* a, const uint32_t* b) {
    asm volatile(
        "mma.sync.aligned.m16n8k16.row.col.f32.bf16.bf16.f32 "
        "{%0,%1,%2,%3}, {%4,%5,%6,%7}, {%8,%9}, {%0,%1,%2,%3};"
        : "+f"(d[0]), "+f"(d[1]), "+f"(d[2]), "+f"(d[3])
        : "r"(a[0]), "r"(a[1]), "r"(a[2]), "r"(a[3]), "r"(b[0]), "r"(b[1]));
}
__device__ __forceinline__ unsigned ld_acq(const unsigned* p) {
    unsigned v;
    asm volatile("ld.acquire.gpu.global.u32 %0, [%1];" : "=r"(v) : "l"(p));
    return v;
}

// ---------------- init ----------------
__global__ void init_kernel() {
    int tid = blockIdx.x * blockDim.x + threadIdx.x;
    if (tid < 2) g_bar[tid] = 0u;
    for (int i = tid; i < 4 * BSZ * HSZ; i += gridDim.x * blockDim.x)
        g_hbuf[i] = 0.f;
}

// ---------------- split f32 -> bf16 hi + lo ----------------
__global__ void cvt_split_kernel(const float* __restrict__ src,
                                 __nv_bfloat16* __restrict__ hi,
                                 __nv_bfloat16* __restrict__ lo, int n4) {
    int stride = gridDim.x * blockDim.x;
    const float4* s4 = (const float4*)src;
    unsigned long long* h8 = (unsigned long long*)hi;
    unsigned long long* l8 = (unsigned long long*)lo;
    for (int i = blockIdx.x * blockDim.x + threadIdx.x; i < n4; i += stride) {
        float4 v = s4[i];
        __nv_bfloat16 h0 = __float2bfloat16_rn(v.x);
        __nv_bfloat16 h1 = __float2bfloat16_rn(v.y);
        __nv_bfloat16 h2 = __float2bfloat16_rn(v.z);
        __nv_bfloat16 h3 = __float2bfloat16_rn(v.w);
        __nv_bfloat16 l0 = __float2bfloat16_rn(v.x - __bfloat162float(h0));
        __nv_bfloat16 l1 = __float2bfloat16_rn(v.y - __bfloat162float(h1));
        __nv_bfloat16 l2 = __float2bfloat16_rn(v.z - __bfloat162float(h2));
        __nv_bfloat16 l3 = __float2bfloat16_rn(v.w - __bfloat162float(h3));
        unsigned long long ph =
            (unsigned long long)__bfloat16_as_ushort(h0) |
            ((unsigned long long)__bfloat16_as_ushort(h1) << 16) |
            ((unsigned long long)__bfloat16_as_ushort(h2) << 32) |
            ((unsigned long long)__bfloat16_as_ushort(h3) << 48);
        unsigned long long pl =
            (unsigned long long)__bfloat16_as_ushort(l0) |
            ((unsigned long long)__bfloat16_as_ushort(l1) << 16) |
            ((unsigned long long)__bfloat16_as_ushort(l2) << 32) |
            ((unsigned long long)__bfloat16_as_ushort(l3) << 48);
        h8[i] = ph;
        l8[i] = pl;
    }
}

// ---------------- HMMA logits GEMM (unchanged from R7) ----------------
#define LOGITS_SMEM 131072
__global__ __launch_bounds__(256, 1) void logits_hmma_kernel(
    const __nv_bfloat16* __restrict__ Ahi, const __nv_bfloat16* __restrict__ Alo,
    const __nv_bfloat16* __restrict__ Whi, const __nv_bfloat16* __restrict__ Wlo,
    const float* __restrict__ bias, float* __restrict__ out)
{
    extern __shared__ char smem[];
    __shared__ float sbias[128];
    const int tid = threadIdx.x, lane = tid & 31, w = tid >> 5;
    const int wm = w >> 1, wn = w & 1;
    const int n0 = blockIdx.x * 128;
    const int m0 = blockIdx.y * 128;
    const uint32_t sb = smem_u32(smem);

    if (tid < 128) sbias[tid] = bias[n0 + tid];

    auto issue = [&](int c, int s) {
        uint32_t st = sb + s * 65536;
#pragma unroll
        for (int i = 0; i < 4; i++) {
            int lin = tid + i * 256;
            int row = lin >> 3, ch = lin & 7;
            uint32_t phys = row * 128 + ((ch ^ (row & 7)) << 4);
            size_t ga = (size_t)(m0 + row) * HSZ + c * 64 + ch * 8;
            size_t gb = (size_t)(n0 + row) * HSZ + c * 64 + ch * 8;
            cp16(st + phys,         Ahi + ga);
            cp16(st + 16384 + phys, Alo + ga);
            cp16(st + 32768 + phys, Whi + gb);
            cp16(st + 49152 + phys, Wlo + gb);
        }
        asm volatile("cp.async.commit_group;" ::: "memory");
    };

    float d[2][8][4];
#pragma unroll
    for (int mt = 0; mt < 2; mt++)
#pragma unroll
        for (int nt = 0; nt < 8; nt++)
#pragma unroll
            for (int j = 0; j < 4; j++) d[mt][nt][j] = 0.f;

    issue(0, 0);

    for (int c = 0; c < 4; c++) {
        const int s = c & 1;
        if (c < 3) {
            issue(c + 1, s ^ 1);
            asm volatile("cp.async.wait_group 1;" ::: "memory");
        } else {
            asm volatile("cp.async.wait_group 0;" ::: "memory");
        }
        __syncthreads();

        const uint32_t st = sb + s * 65536;
#pragma unroll
        for (int ks = 0; ks < 4; ks++) {
            uint32_t ahf[2][4], alf[2][4];
#pragma unroll
            for (int mt = 0; mt < 2; mt++) {
                int row = wm * 32 + mt * 16 + (lane & 7) + ((lane >> 3) & 1) * 8;
                int ch = ks * 2 + ((lane >> 4) & 1);
                uint32_t ad = st + row * 128 + ((ch ^ (row & 7)) << 4);
                ldm_x4(ahf[mt], ad);
                ldm_x4(alf[mt], ad + 16384);
            }
            uint32_t bhf[8][2], blf[8][2];
#pragma unroll
            for (int nt2 = 0; nt2 < 4; nt2++) {
                int row = wn * 64 + nt2 * 16 + (lane & 7) + ((lane >> 4) & 1) * 8;
                int ch = ks * 2 + ((lane >> 3) & 1);
                uint32_t ad = st + 32768 + row * 128 + ((ch ^ (row & 7)) << 4);
                uint32_t q[4];
                ldm_x4(q, ad);
                bhf[2 * nt2][0] = q[0]; bhf[2 * nt2][1] = q[1];
                bhf[2 * nt2 + 1][0] = q[2]; bhf[2 * nt2 + 1][1] = q[3];
                ldm_x4(q, ad + 16384);
                blf[2 * nt2][0] = q[0]; blf[2 * nt2][1] = q[1];
                blf[2 * nt2 + 1][0] = q[2]; blf[2 * nt2 + 1][1] = q[3];
            }
#pragma unroll
            for (int mt = 0; mt < 2; mt++)
#pragma unroll
                for (int nt = 0; nt < 8; nt++) {
                    mma_bf16(d[mt][nt], ahf[mt], bhf[nt]);
                    mma_bf16(d[mt][nt], ahf[mt], blf[nt]);
                    mma_bf16(d[mt][nt], alf[mt], bhf[nt]);
                }
        }
        __syncthreads();
    }

#pragma unroll
    for (int mt = 0; mt < 2; mt++) {
        int mrow = m0 + wm * 32 + mt * 16 + (lane >> 2);
#pragma unroll
        for (int half = 0; half < 2; half++) {
            int m = mrow + half * 8;
            int t = m >> 4, b = m & 15;
            float* dst = out + ((long)b * TSZ + t) * (long)VSZ + n0;
#pragma unroll
            for (int nt = 0; nt < 8; nt++) {
                int lc = wn * 64 + nt * 8 + (lane & 3) * 2;
                float2 v;
                v.x = d[mt][nt][half * 2 + 0] + sbias[lc];
                v.y = d[mt][nt][half * 2 + 1] + sbias[lc + 1];
                *(float2*)(dst + lc) = v;
            }
        }
    }
}

// ---------------- SGEMM (x-proj layer 0 only now) ----------------
template <int MODE>
__global__ __launch_bounds__(256) void sgemm_kernel(
    const float* __restrict__ A, const int* __restrict__ gidx,
    const float* __restrict__ Wt, const float* __restrict__ bias1,
    const float* __restrict__ bias2, float* __restrict__ C,
    int M, int N, int K)
{
    __shared__ float As[16][128];
    __shared__ float Bs[16][128];

    const int tid = threadIdx.x;
    const int n0 = blockIdx.x * 128;
    const int m0 = blockIdx.y * 128;

    const int lr = tid >> 2;
    const int lc = (tid & 3) << 2;

    const float* ap0;
    const float* ap1;
    {
        int mA0 = m0 + lr, mA1 = m0 + lr + 64;
        if (MODE == 0) {
            int t0 = mA0 >> 4, b0 = mA0 & 15;
            int t1 = mA1 >> 4, b1 = mA1 & 15;
            ap0 = A + (long)gidx[b0 * TSZ + t0] * K;
            ap1 = A + (long)gidx[b1 * TSZ + t1] * K;
        } else {
            ap0 = A + (long)mA0 * K;
            ap1 = A + (long)mA1 * K;
        }
    }
    const float* bp0 = Wt + (long)(n0 + lr) * K;
    const float* bp1 = Wt + (long)(n0 + lr + 64) * K;

    const int ty = tid >> 4, tx = tid & 15;
    const int row = ty << 3, col = tx << 3;

    unsigned long long acc[8][4];
#pragma unroll
    for (int i = 0; i < 8; i++)
#pragma unroll
        for (int j = 0; j < 4; j++) acc[i][j] = 0ULL;

    for (int kt = 0; kt < K; kt += 16) {
        float4 a0 = *(const float4*)(ap0 + kt + lc);
        float4 a1 = *(const float4*)(ap1 + kt + lc);
        float4 w0 = *(const float4*)(bp0 + kt + lc);
        float4 w1 = *(const float4*)(bp1 + kt + lc);
        __syncthreads();
        As[lc + 0][lr] = a0.x; As[lc + 1][lr] = a0.y;
        As[lc + 2][lr] = a0.z; As[lc + 3][lr] = a0.w;
        As[lc + 0][lr + 64] = a1.x; As[lc + 1][lr + 64] = a1.y;
        As[lc + 2][lr + 64] = a1.z; As[lc + 3][lr + 64] = a1.w;
        Bs[lc + 0][lr] = w0.x; Bs[lc + 1][lr] = w0.y;
        Bs[lc + 2][lr] = w0.z; Bs[lc + 3][lr] = w0.w;
        Bs[lc + 0][lr + 64] = w1.x; Bs[lc + 1][lr + 64] = w1.y;
        Bs[lc + 2][lr + 64] = w1.z; Bs[lc + 3][lr + 64] = w1.w;
        __syncthreads();

#pragma unroll
        for (int k = 0; k < 16; k++) {
            float4 av0 = *(const float4*)&As[k][row];
            float4 av1 = *(const float4*)&As[k][row + 4];
            float4 bq0 = *(const float4*)&Bs[k][col];
            float4 bq1 = *(const float4*)&Bs[k][col + 4];
            unsigned long long bv0 = pack2(bq0.x, bq0.y);
            unsigned long long bv1 = pack2(bq0.z, bq0.w);
            unsigned long long bv2 = pack2(bq1.x, bq1.y);
            unsigned long long bv3 = pack2(bq1.z, bq1.w);
            float av[8] = {av0.x, av0.y, av0.z, av0.w, av1.x, av1.y, av1.z, av1.w};
#pragma unroll
            for (int i = 0; i < 8; i++) {
                unsigned long long a2 = pack_dup(av[i]);
                FMA_F32X2(acc[i][0], a2, bv0);
                FMA_F32X2(acc[i][1], a2, bv1);
                FMA_F32X2(acc[i][2], a2, bv2);
                FMA_F32X2(acc[i][3], a2, bv3);
            }
        }
    }

#pragma unroll
    for (int i = 0; i < 8; i++) {
        int m = m0 + row + i;
        long base = (long)m * N;
#pragma unroll
        for (int j = 0; j < 4; j++) {
            int n = n0 + col + 2 * j;
            float b0 = bias1[n] + (bias2 ? bias2[n] : 0.f);
            float b1 = bias1[n + 1] + (bias2 ? bias2[n + 1] : 0.f);
            C[base + n] = lo32(acc[i][j]) + b0;
            C[base + n + 1] = hi32(acc[i][j]) + b1;
        }
    }
}

// ---------------- fused wavefront 2-layer LSTM ----------------
// 128 CTAs x 256 thr. CTA<64: layer 0 (xproj0 precomputed). CTA>=64: layer 1,
// one step behind, computing its input projection on the fly from h1s[t] with
// W_ih1 resident in SMEM. bar0 = layer-0 progress, bar1 = layer-1 progress.
// Dyn smem (floats): Ws2[4096] | Wi2[4096] | hs_s[4096] | xs_s[4096] | gbuf[272]
#define FUSED_SMEM ((16384 + 272) * 4)
__global__ __launch_bounds__(256, 1) void fused_lstm_kernel(
    const float* __restrict__ xproj0, const float* __restrict__ W_hh0,
    const float* __restrict__ W_ih1, const float* __restrict__ W_hh1,
    const float* __restrict__ b_ih1, const float* __restrict__ b_hh1,
    float* __restrict__ hbuf,   // [4][B*H]: L0 ping/pong, L1 ping/pong
    float* __restrict__ h1s, float* __restrict__ h2s,
    float* __restrict__ hf0, float* __restrict__ cf0,
    float* __restrict__ hf1, float* __restrict__ cf1,
    unsigned* __restrict__ bars)
{
    extern __shared__ float sm[];
    float* Ws2  = sm;            // W_hh pairs
    float* Wi2  = sm + 4096;     // W_ih1 pairs (layer 1)
    float* hs_s = sm + 8192;     // recurrent h stage
    float* xs_s = sm + 12288;    // layer-1 x stage (= h1s[t])
    float* gbuf = sm + 16384;    // [16][17]

    const int tid = threadIdx.x;
    const bool L1k = (blockIdx.x >= 64);
    const int cta = L1k ? blockIdx.x - 64 : blockIdx.x;
    const int j0 = cta * 4;

    // preload weights: 16 gate rows (r = g*4+jj -> row g*H + j0 + jj)
    const float* Whh = L1k ? W_hh1 : W_hh0;
    for (int idx = tid; idx < 16 * HSZ; idx += 256) {
        int k = idx >> 4, r = idx & 15;
        int g = r >> 2, jj = r & 3;
        int wrow = (g * HSZ + j0 + jj) * HSZ + k;
        int soff = (k >> 1) * 32 + r * 2 + (k & 1);
        Ws2[soff] = Whh[wrow];
        if (L1k) Wi2[soff] = W_ih1[wrow];
    }
    __syncthreads();

    const int b = tid >> 4, r = tid & 15;
    const int gcol = (r >> 2) * HSZ + j0 + (r & 3);
    const int ub = tid >> 2, ujj = tid & 3;
    const float biasv = L1k ? (b_ih1[gcol] + b_hh1[gcol]) : 0.f;

    float* base = hbuf + (L1k ? 2 * BSZ * HSZ : 0);
    float* pp[2] = {base, base + BSZ * HSZ};
    float* hsout = L1k ? h2s : h1s;
    float* hfin = L1k ? hf1 : hf0;
    float* cfin = L1k ? cf1 : cf0;

    float c_st = 0.f, h_st = 0.f;

    for (int t = 0; t < TSZ; t++) {
        // wait: L0 needs all L0 done step t-1; L1 needs L0 done step t AND L1 done t-1
        if (tid == 0) {
            unsigned w0 = L1k ? 64u * (t + 1) : 64u * t;
            while (ld_acq(&bars[0]) < w0) {}
            if (L1k && t > 0) {
                unsigned w1 = 64u * t;
                while (ld_acq(&bars[1]) < w1) {}
            }
        }
        __syncthreads();

        // stage h(t-1) [and x = h1s[t] for layer 1]
        {
            const float4* src = (const float4*)pp[t & 1];
            float4* dst = (float4*)hs_s;
#pragma unroll
            for (int j = 0; j < 4; j++) dst[tid + 256 * j] = __ldcg(src + tid + 256 * j);
            if (L1k) {
                const float4* xsrc = (const float4*)(h1s + (size_t)t * BSZ * HSZ);
                float4* xdst = (float4*)xs_s;
#pragma unroll
                for (int j = 0; j < 4; j++) xdst[tid + 256 * j] = __ldcg(xsrc + tid + 256 * j);
            }
        }
        __syncthreads();

        // recurrent dot (+ input-proj dot for layer 1)
        unsigned long long accA = 0ULL, accB = 0ULL;
        const unsigned long long* hrow = (const unsigned long long*)(hs_s + b * HSZ);
#pragma unroll 16
        for (int k2 = 0; k2 < 128; k2 += 2) {
            unsigned long long h0 = hrow[k2];
            unsigned long long h1 = hrow[k2 + 1];
            unsigned long long w0 = *(const unsigned long long*)&Ws2[k2 * 32 + r * 2];
            unsigned long long w1 = *(const unsigned long long*)&Ws2[(k2 + 1) * 32 + r * 2];
            FMA_F32X2(accA, h0, w0);
            FMA_F32X2(accB, h1, w1);
        }
        float acc = (lo32(accA) + hi32(accA)) + (lo32(accB) + hi32(accB));
        if (L1k) {
            unsigned long long accC = 0ULL, accD = 0ULL;
            const unsigned long long* xrow = (const unsigned long long*)(xs_s + b * HSZ);
#pragma unroll 16
            for (int k2 = 0; k2 < 128; k2 += 2) {
                unsigned long long x0 = xrow[k2];
                unsigned long long x1 = xrow[k2 + 1];
                unsigned long long w0 = *(const unsigned long long*)&Wi2[k2 * 32 + r * 2];
                unsigned long long w1 = *(const unsigned long long*)&Wi2[(k2 + 1) * 32 + r * 2];
                FMA_F32X2(accC, x0, w0);
                FMA_F32X2(accD, x1, w1);
            }
            acc += (lo32(accC) + hi32(accC)) + (lo32(accD) + hi32(accD)) + biasv;
        } else {
            acc += xproj0[((size_t)t * BSZ + b) * G4H + gcol];
        }
        gbuf[b * 17 + r] = acc;
        __syncthreads();

        if (tid < 64) {
            float iv = gbuf[ub * 17 + ujj];
            float fv = gbuf[ub * 17 + 4 + ujj];
            float gv = gbuf[ub * 17 + 8 + ujj];
            float ov = gbuf[ub * 17 + 12 + ujj];
            iv = 1.f / (1.f + expf(-iv));
            fv = 1.f / (1.f + expf(-fv));
            ov = 1.f / (1.f + expf(-ov));
            gv = tanhf(gv);
            c_st = fv * c_st + iv * gv;
            h_st = ov * tanhf(c_st);
            int hcol = j0 + ujj;
            __stcg(&pp[(t + 1) & 1][ub * HSZ + hcol], h_st);
            __stcg(&hsout[((size_t)t * BSZ + ub) * HSZ + hcol], h_st);
        }
        __syncthreads();

        if (tid == 0) {
            unsigned* bar = &bars[L1k ? 1 : 0];
            asm volatile("red.release.gpu.global.add.u32 [%0], 1;" :: "l"(bar) : "memory");
        }
        __syncthreads();
    }

    if (tid < 64) {
        hfin[ub * HSZ + j0 + ujj] = h_st;
        cfin[ub * HSZ + j0 + ujj] = c_st;
    }
}

// ---------------- launch ----------------
extern "C" void kernel_launch(void* const* d_in, const int* in_sizes, int n_in,
                              void* d_out, int out_size) {
    const int*   x     = (const int*)d_in[0];
    const float* emb   = (const float*)d_in[1];
    const float* W_ih0 = (const float*)d_in[2];
    const float* W_hh0 = (const float*)d_in[3];
    const float* b_ih0 = (const float*)d_in[4];
    const float* b_hh0 = (const float*)d_in[5];
    const float* W_ih1 = (const float*)d_in[6];
    const float* W_hh1 = (const float*)d_in[7];
    const float* b_ih1 = (const float*)d_in[8];
    const float* b_hh1 = (const float*)d_in[9];
    const float* W_fc  = (const float*)d_in[10];
    const float* b_fc  = (const float*)d_in[11];
    float* out = (float*)d_out;

    float *xp0, *h1s, *h2s, *hb;
    unsigned* bars;
    __nv_bfloat16 *whi, *wlo, *ahi, *alo;
    cudaGetSymbolAddress((void**)&xp0,  g_xproj0);
    cudaGetSymbolAddress((void**)&h1s,  g_h1s);
    cudaGetSymbolAddress((void**)&h2s,  g_h2s);
    cudaGetSymbolAddress((void**)&hb,   g_hbuf);
    cudaGetSymbolAddress((void**)&bars, g_bar);
    cudaGetSymbolAddress((void**)&whi,  g_whi);
    cudaGetSymbolAddress((void**)&wlo,  g_wlo);
    cudaGetSymbolAddress((void**)&ahi,  g_ahi);
    cudaGetSymbolAddress((void**)&alo,  g_alo);

    cudaFuncSetAttribute(logits_hmma_kernel,
                         cudaFuncAttributeMaxDynamicSharedMemorySize, LOGITS_SMEM);
    cudaFuncSetAttribute(fused_lstm_kernel,
                         cudaFuncAttributeMaxDynamicSharedMemorySize, FUSED_SMEM);

    const long OFF_H = (long)BSZ * TSZ * VSZ;           // logits size
    const long OFF_C = OFF_H + 2L * BSZ * HSZ;
    const bool ws = ((long)out_size >= OFF_C + 2L * BSZ * HSZ);
    float* hf0 = ws ? out + OFF_H : nullptr;
    float* hf1 = ws ? out + OFF_H + BSZ * HSZ : nullptr;
    float* cf0 = ws ? out + OFF_C : nullptr;
    float* cf1 = ws ? out + OFF_C + BSZ * HSZ : nullptr;
    // if workspace flags missing, still need valid pointers (reuse scratch)
    if (!ws) { hf0 = hb; hf1 = hb; cf0 = hb; cf1 = hb; }

    init_kernel<<<8, 256>>>();
    cvt_split_kernel<<<2048, 256>>>(W_fc, whi, wlo, VSZ * HSZ / 4);

    dim3 gproj(G4H / 128, MTOT / 128);   // (8, 32)
    sgemm_kernel<0><<<gproj, 256>>>(emb, x, W_ih0, b_ih0, b_hh0, xp0,
                                    MTOT, G4H, ESZ);
    fused_lstm_kernel<<<128, 256, FUSED_SMEM>>>(
        xp0, W_hh0, W_ih1, W_hh1, b_ih1, b_hh1,
        hb, h1s, h2s, hf0, cf0, hf1, cf1, bars);
    cvt_split_kernel<<<512, 256>>>(h2s, ahi, alo, MTOT * HSZ / 4);
    dim3 glog(VSZ / 128, MTOT / 128);    // (250, 32)
    logits_hmma_kernel<<<glog, 256, LOGITS_SMEM>>>(ahi, alo, whi, wlo, b_fc, out);
}

// round 9
// speedup vs baseline: 1.9600x; 1.0012x over previous
#include <cuda_runtime.h>
#include <cuda_bf16.h>
#include <cstdint>

// Problem constants  (V, E, H, B, T = 32000, 128, 256, 16, 256)
#define VSZ 32000
#define ESZ 128
#define HSZ 256
#define BSZ 16
#define TSZ 256
#define G4H 1024          // 4*H
#define MTOT 4096         // T*B

// ---------------- device scratch (no cudaMalloc allowed) ----------------
__device__ float    g_xproj0[MTOT * G4H];   // [T,B,4H]
__device__ float    g_h1s[MTOT * HSZ];      // [T,B,H]
__device__ float    g_hbuf[4 * BSZ * HSZ];  // L0 ping/pong, L1 ping/pong
__device__ unsigned g_bar[2];
// split-bf16 operands for the HMMA logits GEMM
__device__ __nv_bfloat16 g_whi[VSZ * HSZ];
__device__ __nv_bfloat16 g_wlo[VSZ * HSZ];
__device__ __nv_bfloat16 g_ahi[MTOT * HSZ];   // written by LSTM layer-1
__device__ __nv_bfloat16 g_alo[MTOT * HSZ];

// ---------------- helpers ----------------
#define FMA_F32X2(acc, a, b) \
    asm("fma.rn.f32x2 %0, %1, %2, %0;" : "+l"(acc) : "l"(a), "l"(b))

__device__ __forceinline__ unsigned long long pack_dup(float v) {
    unsigned long long r;
    asm("mov.b64 %0, {%1, %1};" : "=l"(r) : "f"(v));
    return r;
}
__device__ __forceinline__ unsigned long long pack2(float x, float y) {
    unsigned long long r;
    asm("mov.b64 %0, {%1, %2};" : "=l"(r) : "f"(x), "f"(y));
    return r;
}
__device__ __forceinline__ float lo32(unsigned long long v) {
    return __uint_as_float((unsigned)(v & 0xffffffffULL));
}
__device__ __forceinline__ float hi32(unsigned long long v) {
    return __uint_as_float((unsigned)(v >> 32));
}
__device__ __forceinline__ uint32_t smem_u32(const void* p) {
    uint32_t a;
    asm("{ .reg .u64 t; cvta.to.shared.u64 t, %1; cvt.u32.u64 %0, t; }"
        : "=r"(a) : "l"(p));
    return a;
}
__device__ __forceinline__ void cp16(uint32_t s, const void* g) {
    asm volatile("cp.async.cg.shared.global [%0], [%1], 16;"
                 :: "r"(s), "l"(g) : "memory");
}
__device__ __forceinline__ void ldm_x4(uint32_t* r, uint32_t addr) {
    asm volatile("ldmatrix.sync.aligned.m8n8.x4.shared.b16 {%0,%1,%2,%3}, [%4];"
                 : "=r"(r[0]), "=r"(r[1]), "=r"(r[2]), "=r"(r[3]) : "r"(addr));
}
__device__ __forceinline__ void mma_bf16(float* d, const uint32_t* a, const uint32_t* b) {
    asm volatile(
        "mma.sync.aligned.m16n8k16.row.col.f32.bf16.bf16.f32 "
        "{%0,%1,%2,%3}, {%4,%5,%6,%7}, {%8,%9}, {%0,%1,%2,%3};"
        : "+f"(d[0]), "+f"(d[1]), "+f"(d[2]), "+f"(d[3])
        : "r"(a[0]), "r"(a[1]), "r"(a[2]), "r"(a[3]), "r"(b[0]), "r"(b[1]));
}
__device__ __forceinline__ unsigned ld_acq(const unsigned* p) {
    unsigned v;
    asm volatile("ld.acquire.gpu.global.u32 %0, [%1];" : "=r"(v) : "l"(p));
    return v;
}

// ---------------- init ----------------
__global__ void init_kernel() {
    int tid = blockIdx.x * blockDim.x + threadIdx.x;
    if (tid < 2) g_bar[tid] = 0u;
    for (int i = tid; i < 4 * BSZ * HSZ; i += gridDim.x * blockDim.x)
        g_hbuf[i] = 0.f;
}

// ---------------- split f32 -> bf16 hi + lo (weights) ----------------
__global__ void cvt_split_kernel(const float* __restrict__ src,
                                 __nv_bfloat16* __restrict__ hi,
                                 __nv_bfloat16* __restrict__ lo, int n4) {
    int stride = gridDim.x * blockDim.x;
    const float4* s4 = (const float4*)src;
    unsigned long long* h8 = (unsigned long long*)hi;
    unsigned long long* l8 = (unsigned long long*)lo;
    for (int i = blockIdx.x * blockDim.x + threadIdx.x; i < n4; i += stride) {
        float4 v = s4[i];
        __nv_bfloat16 h0 = __float2bfloat16_rn(v.x);
        __nv_bfloat16 h1 = __float2bfloat16_rn(v.y);
        __nv_bfloat16 h2 = __float2bfloat16_rn(v.z);
        __nv_bfloat16 h3 = __float2bfloat16_rn(v.w);
        __nv_bfloat16 l0 = __float2bfloat16_rn(v.x - __bfloat162float(h0));
        __nv_bfloat16 l1 = __float2bfloat16_rn(v.y - __bfloat162float(h1));
        __nv_bfloat16 l2 = __float2bfloat16_rn(v.z - __bfloat162float(h2));
        __nv_bfloat16 l3 = __float2bfloat16_rn(v.w - __bfloat162float(h3));
        unsigned long long ph =
            (unsigned long long)__bfloat16_as_ushort(h0) |
            ((unsigned long long)__bfloat16_as_ushort(h1) << 16) |
            ((unsigned long long)__bfloat16_as_ushort(h2) << 32) |
            ((unsigned long long)__bfloat16_as_ushort(h3) << 48);
        unsigned long long pl =
            (unsigned long long)__bfloat16_as_ushort(l0) |
            ((unsigned long long)__bfloat16_as_ushort(l1) << 16) |
            ((unsigned long long)__bfloat16_as_ushort(l2) << 32) |
            ((unsigned long long)__bfloat16_as_ushort(l3) << 48);
        h8[i] = ph;
        l8[i] = pl;
    }
}

// ---------------- SGEMM (x-proj layer 0) ----------------
template <int MODE>
__global__ __launch_bounds__(256) void sgemm_kernel(
    const float* __restrict__ A, const int* __restrict__ gidx,
    const float* __restrict__ Wt, const float* __restrict__ bias1,
    const float* __restrict__ bias2, float* __restrict__ C,
    int M, int N, int K)
{
    __shared__ float As[16][128];
    __shared__ float Bs[16][128];

    const int tid = threadIdx.x;
    const int n0 = blockIdx.x * 128;
    const int m0 = blockIdx.y * 128;

    const int lr = tid >> 2;
    const int lc = (tid & 3) << 2;

    const float* ap0;
    const float* ap1;
    {
        int mA0 = m0 + lr, mA1 = m0 + lr + 64;
        if (MODE == 0) {
            int t0 = mA0 >> 4, b0 = mA0 & 15;
            int t1 = mA1 >> 4, b1 = mA1 & 15;
            ap0 = A + (long)gidx[b0 * TSZ + t0] * K;
            ap1 = A + (long)gidx[b1 * TSZ + t1] * K;
        } else {
            ap0 = A + (long)mA0 * K;
            ap1 = A + (long)mA1 * K;
        }
    }
    const float* bp0 = Wt + (long)(n0 + lr) * K;
    const float* bp1 = Wt + (long)(n0 + lr + 64) * K;

    const int ty = tid >> 4, tx = tid & 15;
    const int row = ty << 3, col = tx << 3;

    unsigned long long acc[8][4];
#pragma unroll
    for (int i = 0; i < 8; i++)
#pragma unroll
        for (int j = 0; j < 4; j++) acc[i][j] = 0ULL;

    for (int kt = 0; kt < K; kt += 16) {
        float4 a0 = *(const float4*)(ap0 + kt + lc);
        float4 a1 = *(const float4*)(ap1 + kt + lc);
        float4 w0 = *(const float4*)(bp0 + kt + lc);
        float4 w1 = *(const float4*)(bp1 + kt + lc);
        __syncthreads();
        As[lc + 0][lr] = a0.x; As[lc + 1][lr] = a0.y;
        As[lc + 2][lr] = a0.z; As[lc + 3][lr] = a0.w;
        As[lc + 0][lr + 64] = a1.x; As[lc + 1][lr + 64] = a1.y;
        As[lc + 2][lr + 64] = a1.z; As[lc + 3][lr + 64] = a1.w;
        Bs[lc + 0][lr] = w0.x; Bs[lc + 1][lr] = w0.y;
        Bs[lc + 2][lr] = w0.z; Bs[lc + 3][lr] = w0.w;
        Bs[lc + 0][lr + 64] = w1.x; Bs[lc + 1][lr + 64] = w1.y;
        Bs[lc + 2][lr + 64] = w1.z; Bs[lc + 3][lr + 64] = w1.w;
        __syncthreads();

#pragma unroll
        for (int k = 0; k < 16; k++) {
            float4 av0 = *(const float4*)&As[k][row];
            float4 av1 = *(const float4*)&As[k][row + 4];
            float4 bq0 = *(const float4*)&Bs[k][col];
            float4 bq1 = *(const float4*)&Bs[k][col + 4];
            unsigned long long bv0 = pack2(bq0.x, bq0.y);
            unsigned long long bv1 = pack2(bq0.z, bq0.w);
            unsigned long long bv2 = pack2(bq1.x, bq1.y);
            unsigned long long bv3 = pack2(bq1.z, bq1.w);
            float av[8] = {av0.x, av0.y, av0.z, av0.w, av1.x, av1.y, av1.z, av1.w};
#pragma unroll
            for (int i = 0; i < 8; i++) {
                unsigned long long a2 = pack_dup(av[i]);
                FMA_F32X2(acc[i][0], a2, bv0);
                FMA_F32X2(acc[i][1], a2, bv1);
                FMA_F32X2(acc[i][2], a2, bv2);
                FMA_F32X2(acc[i][3], a2, bv3);
            }
        }
    }

#pragma unroll
    for (int i = 0; i < 8; i++) {
        int m = m0 + row + i;
        long base = (long)m * N;
#pragma unroll
        for (int j = 0; j < 4; j++) {
            int n = n0 + col + 2 * j;
            float b0 = bias1[n] + (bias2 ? bias2[n] : 0.f);
            float b1 = bias1[n + 1] + (bias2 ? bias2[n + 1] : 0.f);
            C[base + n] = lo32(acc[i][j]) + b0;
            C[base + n + 1] = hi32(acc[i][j]) + b1;
        }
    }
}

// ================= MEGA KERNEL: fused LSTM wavefront + overlapped logits ====
// grid = 8128.  bid<64: LSTM L0.  64<=bid<128: LSTM L1 (writes ahi/alo).
// bid>=128: logits HMMA CTA for (my = (bid-128)/250, nx = (bid-128)%250),
// spin-waits on bar1 until layer-1 finished timestep 8*my+7.
// Dyn smem 66624B:
//   LSTM:   Ws2[4096] Wi2[4096] hs_s[4096] xs_s[4096] gbuf[272] (floats)
//   logits: Ahi@0 Alo@16K Whi@32K Wlo@48K (bf16, swizzled) + bias@64K (128 f)
#define MEGA_SMEM 66624
__global__ __launch_bounds__(256, 2) void mega_kernel(
    const float* __restrict__ xproj0, const float* __restrict__ W_hh0,
    const float* __restrict__ W_ih1, const float* __restrict__ W_hh1,
    const float* __restrict__ b_ih1, const float* __restrict__ b_hh1,
    float* __restrict__ hbuf, float* __restrict__ h1s,
    __nv_bfloat16* __restrict__ ahi, __nv_bfloat16* __restrict__ alo,
    const __nv_bfloat16* __restrict__ Whi, const __nv_bfloat16* __restrict__ Wlo,
    const float* __restrict__ bias, float* __restrict__ out,
    float* __restrict__ hf0, float* __restrict__ cf0,
    float* __restrict__ hf1, float* __restrict__ cf1,
    unsigned* __restrict__ bars)
{
    extern __shared__ float sm[];
    const int tid = threadIdx.x;

    if (blockIdx.x < 128) {
        // ================= LSTM wavefront =================
        float* Ws2  = sm;
        float* Wi2  = sm + 4096;
        float* hs_s = sm + 8192;
        float* xs_s = sm + 12288;
        float* gbuf = sm + 16384;

        const bool L1k = (blockIdx.x >= 64);
        const int cta = L1k ? blockIdx.x - 64 : blockIdx.x;
        const int j0 = cta * 4;

        const float* Whh = L1k ? W_hh1 : W_hh0;
        for (int idx = tid; idx < 16 * HSZ; idx += 256) {
            int k = idx >> 4, r = idx & 15;
            int g = r >> 2, jj = r & 3;
            int wrow = (g * HSZ + j0 + jj) * HSZ + k;
            int soff = (k >> 1) * 32 + r * 2 + (k & 1);
            Ws2[soff] = Whh[wrow];
            if (L1k) Wi2[soff] = W_ih1[wrow];
        }
        __syncthreads();

        const int b = tid >> 4, r = tid & 15;
        const int gcol = (r >> 2) * HSZ + j0 + (r & 3);
        const int ub = tid >> 2, ujj = tid & 3;
        const float biasv = L1k ? (b_ih1[gcol] + b_hh1[gcol]) : 0.f;

        float* base = hbuf + (L1k ? 2 * BSZ * HSZ : 0);
        float* pp[2] = {base, base + BSZ * HSZ};
        float* hfin = L1k ? hf1 : hf0;
        float* cfin = L1k ? cf1 : cf0;

        float c_st = 0.f, h_st = 0.f;

        for (int t = 0; t < TSZ; t++) {
            if (tid == 0) {
                unsigned w0 = L1k ? 64u * (t + 1) : 64u * t;
                while (ld_acq(&bars[0]) < w0) {}
                if (L1k && t > 0) {
                    unsigned w1 = 64u * t;
                    while (ld_acq(&bars[1]) < w1) {}
                }
            }
            __syncthreads();

            {
                const float4* src = (const float4*)pp[t & 1];
                float4* dst = (float4*)hs_s;
#pragma unroll
                for (int j = 0; j < 4; j++)
                    dst[tid + 256 * j] = __ldcg(src + tid + 256 * j);
                if (L1k) {
                    const float4* xsrc = (const float4*)(h1s + (size_t)t * BSZ * HSZ);
                    float4* xdst = (float4*)xs_s;
#pragma unroll
                    for (int j = 0; j < 4; j++)
                        xdst[tid + 256 * j] = __ldcg(xsrc + tid + 256 * j);
                }
            }
            __syncthreads();

            unsigned long long accA = 0ULL, accB = 0ULL;
            const unsigned long long* hrow = (const unsigned long long*)(hs_s + b * HSZ);
#pragma unroll 16
            for (int k2 = 0; k2 < 128; k2 += 2) {
                unsigned long long h0 = hrow[k2];
                unsigned long long h1v = hrow[k2 + 1];
                unsigned long long w0 = *(const unsigned long long*)&Ws2[k2 * 32 + r * 2];
                unsigned long long w1 = *(const unsigned long long*)&Ws2[(k2 + 1) * 32 + r * 2];
                FMA_F32X2(accA, h0, w0);
                FMA_F32X2(accB, h1v, w1);
            }
            float acc = (lo32(accA) + hi32(accA)) + (lo32(accB) + hi32(accB));
            if (L1k) {
                unsigned long long accC = 0ULL, accD = 0ULL;
                const unsigned long long* xrow = (const unsigned long long*)(xs_s + b * HSZ);
#pragma unroll 16
                for (int k2 = 0; k2 < 128; k2 += 2) {
                    unsigned long long x0 = xrow[k2];
                    unsigned long long x1 = xrow[k2 + 1];
                    unsigned long long w0 = *(const unsigned long long*)&Wi2[k2 * 32 + r * 2];
                    unsigned long long w1 = *(const unsigned long long*)&Wi2[(k2 + 1) * 32 + r * 2];
                    FMA_F32X2(accC, x0, w0);
                    FMA_F32X2(accD, x1, w1);
                }
                acc += (lo32(accC) + hi32(accC)) + (lo32(accD) + hi32(accD)) + biasv;
            } else {
                acc += xproj0[((size_t)t * BSZ + b) * G4H + gcol];
            }
            gbuf[b * 17 + r] = acc;
            __syncthreads();

            if (tid < 64) {
                float iv = gbuf[ub * 17 + ujj];
                float fv = gbuf[ub * 17 + 4 + ujj];
                float gv = gbuf[ub * 17 + 8 + ujj];
                float ov = gbuf[ub * 17 + 12 + ujj];
                iv = 1.f / (1.f + expf(-iv));
                fv = 1.f / (1.f + expf(-fv));
                ov = 1.f / (1.f + expf(-ov));
                gv = tanhf(gv);
                c_st = fv * c_st + iv * gv;
                h_st = ov * tanhf(c_st);
                int hcol = j0 + ujj;
                __stcg(&pp[(t + 1) & 1][ub * HSZ + hcol], h_st);
                if (L1k) {
                    // emit split-bf16 A rows for the logits GEMM
                    __nv_bfloat16 hh = __float2bfloat16_rn(h_st);
                    __nv_bfloat16 hl = __float2bfloat16_rn(h_st - __bfloat162float(hh));
                    size_t am = ((size_t)t * BSZ + ub) * HSZ + hcol;
                    ahi[am] = hh;
                    alo[am] = hl;
                } else {
                    __stcg(&h1s[((size_t)t * BSZ + ub) * HSZ + hcol], h_st);
                }
            }
            __syncthreads();

            if (tid == 0) {
                unsigned* bar = &bars[L1k ? 1 : 0];
                asm volatile("red.release.gpu.global.add.u32 [%0], 1;" :: "l"(bar) : "memory");
            }
            __syncthreads();
        }

        if (tid < 64) {
            hfin[ub * HSZ + j0 + ujj] = h_st;
            cfin[ub * HSZ + j0 + ujj] = c_st;
        }
    } else {
        // ================= logits HMMA =================
        const int idx = blockIdx.x - 128;
        const int my = idx / 250, nx = idx - my * 250;
        const int m0 = my * 128, n0 = nx * 128;
        const int lane = tid & 31, w = tid >> 5;
        const int wm = w >> 1, wn = w & 1;
        const uint32_t sb = smem_u32(sm);
        float* sbias = sm + 16384;

        // wait for layer-1 to finish timestep 8*my+7 (A rows m0..m0+127)
        if (tid == 0) {
            unsigned need = 512u * (my + 1);
            while (ld_acq(&bars[1]) < need) {}
        }
        if (tid < 128) sbias[tid] = bias[n0 + tid];
        __syncthreads();

        float d[2][8][4];
#pragma unroll
        for (int mt = 0; mt < 2; mt++)
#pragma unroll
            for (int nt = 0; nt < 8; nt++)
#pragma unroll
                for (int j = 0; j < 4; j++) d[mt][nt][j] = 0.f;

        for (int c = 0; c < 4; c++) {
            // single-stage load of K-chunk c (cp.async.cg: L2-coherent)
#pragma unroll
            for (int i = 0; i < 4; i++) {
                int lin = tid + i * 256;
                int row = lin >> 3, ch = lin & 7;
                uint32_t phys = row * 128 + ((ch ^ (row & 7)) << 4);
                size_t ga = (size_t)(m0 + row) * HSZ + c * 64 + ch * 8;
                size_t gb = (size_t)(n0 + row) * HSZ + c * 64 + ch * 8;
                cp16(sb + phys,         ahi + ga);
                cp16(sb + 16384 + phys, alo + ga);
                cp16(sb + 32768 + phys, Whi + gb);
                cp16(sb + 49152 + phys, Wlo + gb);
            }
            asm volatile("cp.async.commit_group;" ::: "memory");
            asm volatile("cp.async.wait_group 0;" ::: "memory");
            __syncthreads();

#pragma unroll
            for (int ks = 0; ks < 4; ks++) {
                uint32_t ahf[2][4], alf[2][4];
#pragma unroll
                for (int mt = 0; mt < 2; mt++) {
                    int row = wm * 32 + mt * 16 + (lane & 7) + ((lane >> 3) & 1) * 8;
                    int ch = ks * 2 + ((lane >> 4) & 1);
                    uint32_t ad = sb + row * 128 + ((ch ^ (row & 7)) << 4);
                    ldm_x4(ahf[mt], ad);
                    ldm_x4(alf[mt], ad + 16384);
                }
#pragma unroll
                for (int nt2 = 0; nt2 < 4; nt2++) {
                    int row = wn * 64 + nt2 * 16 + (lane & 7) + ((lane >> 4) & 1) * 8;
                    int ch = ks * 2 + ((lane >> 3) & 1);
                    uint32_t ad = sb + 32768 + row * 128 + ((ch ^ (row & 7)) << 4);
                    uint32_t qh[4], ql[4];
                    ldm_x4(qh, ad);
                    ldm_x4(ql, ad + 16384);
#pragma unroll
                    for (int mt = 0; mt < 2; mt++) {
                        mma_bf16(d[mt][2 * nt2],     ahf[mt], qh);
                        mma_bf16(d[mt][2 * nt2],     ahf[mt], ql);
                        mma_bf16(d[mt][2 * nt2],     alf[mt], qh);
                        mma_bf16(d[mt][2 * nt2 + 1], ahf[mt], qh + 2);
                        mma_bf16(d[mt][2 * nt2 + 1], ahf[mt], ql + 2);
                        mma_bf16(d[mt][2 * nt2 + 1], alf[mt], qh + 2);
                    }
                }
            }
            __syncthreads();
        }

        // epilogue: bias + [t,b]->[b,t] remapped store
#pragma unroll
        for (int mt = 0; mt < 2; mt++) {
            int mrow = m0 + wm * 32 + mt * 16 + (lane >> 2);
#pragma unroll
            for (int half = 0; half < 2; half++) {
                int m = mrow + half * 8;
                int t = m >> 4, b = m & 15;
                float* dst = out + ((long)b * TSZ + t) * (long)VSZ + n0;
#pragma unroll
                for (int nt = 0; nt < 8; nt++) {
                    int lc = wn * 64 + nt * 8 + (lane & 3) * 2;
                    float2 v;
                    v.x = d[mt][nt][half * 2 + 0] + sbias[lc];
                    v.y = d[mt][nt][half * 2 + 1] + sbias[lc + 1];
                    *(float2*)(dst + lc) = v;
                }
            }
        }
    }
}

// ---------------- launch ----------------
extern "C" void kernel_launch(void* const* d_in, const int* in_sizes, int n_in,
                              void* d_out, int out_size) {
    const int*   x     = (const int*)d_in[0];
    const float* emb   = (const float*)d_in[1];
    const float* W_ih0 = (const float*)d_in[2];
    const float* W_hh0 = (const float*)d_in[3];
    const float* b_ih0 = (const float*)d_in[4];
    const float* b_hh0 = (const float*)d_in[5];
    const float* W_ih1 = (const float*)d_in[6];
    const float* W_hh1 = (const float*)d_in[7];
    const float* b_ih1 = (const float*)d_in[8];
    const float* b_hh1 = (const float*)d_in[9];
    const float* W_fc  = (const float*)d_in[10];
    const float* b_fc  = (const float*)d_in[11];
    float* out = (float*)d_out;

    float *xp0, *h1s, *hb;
    unsigned* bars;
    __nv_bfloat16 *whi, *wlo, *ahi, *alo;
    cudaGetSymbolAddress((void**)&xp0,  g_xproj0);
    cudaGetSymbolAddress((void**)&h1s,  g_h1s);
    cudaGetSymbolAddress((void**)&hb,   g_hbuf);
    cudaGetSymbolAddress((void**)&bars, g_bar);
    cudaGetSymbolAddress((void**)&whi,  g_whi);
    cudaGetSymbolAddress((void**)&wlo,  g_wlo);
    cudaGetSymbolAddress((void**)&ahi,  g_ahi);
    cudaGetSymbolAddress((void**)&alo,  g_alo);

    cudaFuncSetAttribute(mega_kernel,
                         cudaFuncAttributeMaxDynamicSharedMemorySize, MEGA_SMEM);

    const long OFF_H = (long)BSZ * TSZ * VSZ;           // logits size
    const long OFF_C = OFF_H + 2L * BSZ * HSZ;
    const bool ws = ((long)out_size >= OFF_C + 2L * BSZ * HSZ);
    float* hf0 = ws ? out + OFF_H : nullptr;
    float* hf1 = ws ? out + OFF_H + BSZ * HSZ : nullptr;
    float* cf0 = ws ? out + OFF_C : nullptr;
    float* cf1 = ws ? out + OFF_C + BSZ * HSZ : nullptr;
    if (!ws) { hf0 = hb; hf1 = hb; cf0 = hb; cf1 = hb; }

    init_kernel<<<8, 256>>>();
    cvt_split_kernel<<<2048, 256>>>(W_fc, whi, wlo, VSZ * HSZ / 4);

    dim3 gproj(G4H / 128, MTOT / 128);   // (8, 32)
    sgemm_kernel<0><<<gproj, 256>>>(emb, x, W_ih0, b_ih0, b_hh0, xp0,
                                    MTOT, G4H, ESZ);

    mega_kernel<<<128 + (VSZ / 128) * (MTOT / 128), 256, MEGA_SMEM>>>(
        xp0, W_hh0, W_ih1, W_hh1, b_ih1, b_hh1,
        hb, h1s, ahi, alo, whi, wlo, b_fc, out,
        hf0, cf0, hf1, cf1, bars);
}